// round 11
// baseline (speedup 1.0000x reference)
#include <cuda_runtime.h>
#include <cstdint>
#include <mma.h>
#include <math.h>
using namespace nvcuda;

#define BATCH 32
#define NSEGC 8
#define SLEN  128
#define TTOT  1024
#define KTAG  16
#define MROWS 32768

// ---------------- device scratch ----------------
__device__ float g_G1 [(size_t)MROWS * 1024];   // stage1 x-gates (packed rows)
__device__ float g_P2 [(size_t)MROWS * 256];    // packed lstm2 input (= packed stage1 out)
__device__ float g_G2 [(size_t)MROWS * 1024];   // stage2 x-gates (packed rows)
__device__ float g_OUT2[(size_t)MROWS * 256];   // stage2 outputs (packed)
__device__ float g_EM [(size_t)MROWS * KTAG];   // emissions (packed)
__device__ float g_Whi[1024 * 256];             // tf32-hi of [Wf;Wb]
__device__ float g_Wlo[1024 * 256];             // tf32-lo of [Wf;Wb]
__device__ float g_bias[1024];                  // bih+bhh, f then b
__device__ int   g_segoff[257];
__device__ int   g_tokmap[MROWS];
__device__ float g_Hf[2][BATCH][128];
__device__ float g_Cf[2][BATCH][128];

// ---------------- helpers ----------------
__device__ __forceinline__ float f2tf(float x)
{
    float r;
    asm("cvt.rna.tf32.f32 %0, %1;" : "=f"(r) : "f"(x));
    return r;
}
__device__ __forceinline__ float sig_fast(float x)
{
    return __fdividef(1.0f, 1.0f + __expf(-x));
}
__device__ __forceinline__ float tanh_fast(float x)
{
    return 1.0f - 2.0f * __fdividef(1.0f, 1.0f + __expf(2.0f * x));
}
// packed fp32x2 FMA (Blackwell FFMA2; PTX-only form)
__device__ __forceinline__ unsigned long long ffma2(
    unsigned long long a, unsigned long long b, unsigned long long c)
{
    unsigned long long d;
    asm("fma.rn.f32x2 %0, %1, %2, %3;" : "=l"(d) : "l"(a), "l"(b), "l"(c));
    return d;
}
__device__ __forceinline__ unsigned long long pk2(float lo, float hi)
{
    unsigned long long r;
    asm("mov.b64 %0, {%1, %2};" : "=l"(r) : "f"(lo), "f"(hi));
    return r;
}
__device__ __forceinline__ void unpk2(unsigned long long v, float& lo, float& hi)
{
    asm("mov.b64 {%0, %1}, %2;" : "=f"(lo), "=f"(hi) : "l"(v));
}
__device__ __forceinline__ unsigned smem_u32(const void* p)
{
    return (unsigned)__cvta_generic_to_shared(p);
}
__device__ __forceinline__ unsigned mapa_u32(unsigned a, unsigned r)
{
    unsigned d;
    asm("mapa.shared::cluster.u32 %0, %1, %2;" : "=r"(d) : "r"(a), "r"(r));
    return d;
}
__device__ __forceinline__ void mbar_init(unsigned a, unsigned cnt)
{
    asm volatile("mbarrier.init.shared.b64 [%0], %1;" :: "r"(a), "r"(cnt) : "memory");
}
__device__ __forceinline__ void mbar_arrive_local(unsigned a)
{
    asm volatile("mbarrier.arrive.shared::cta.b64 _, [%0];" :: "r"(a) : "memory");
}
__device__ __forceinline__ void mbar_arrive_remote(unsigned a)
{
    asm volatile("mbarrier.arrive.release.cluster.shared::cluster.b64 _, [%0];"
                 :: "r"(a) : "memory");
}
__device__ __forceinline__ void mbar_wait_cluster(unsigned a, unsigned phase)
{
    asm volatile(
        "{\n\t"
        ".reg .pred P;\n\t"
        "WLOOP%=:\n\t"
        "mbarrier.try_wait.parity.acquire.cluster.shared::cta.b64 P, [%0], %1;\n\t"
        "@!P bra WLOOP%=;\n\t"
        "}"
        :: "r"(a), "r"(phase) : "memory");
}
__device__ __forceinline__ void st_shared_cluster_f32(unsigned a, float v)
{
    asm volatile("st.shared::cluster.f32 [%0], %1;" :: "r"(a), "f"(v) : "memory");
}
__device__ __forceinline__ void cluster_sync_()
{
    asm volatile("barrier.cluster.arrive.aligned;" ::: "memory");
    asm volatile("barrier.cluster.wait.aligned;" ::: "memory");
}

// ---------------- offsets: warp scan of 256 lengths ----------------
__global__ void k_offsets(const int* __restrict__ lengths)
{
    int lane = threadIdx.x;
    int v[8], s = 0;
#pragma unroll
    for (int i = 0; i < 8; i++) { v[i] = lengths[lane * 8 + i]; s += v[i]; }
    int inc = s;
#pragma unroll
    for (int d = 1; d < 32; d <<= 1) {
        int o = __shfl_up_sync(0xFFFFFFFFu, inc, d);
        if (lane >= d) inc += o;
    }
    int run = inc - s;                    // exclusive prefix of lane sums
#pragma unroll
    for (int i = 0; i < 8; i++) { g_segoff[lane * 8 + i] = run; run += v[i]; }
    if (lane == 31) g_segoff[256] = run;
}

__global__ void k_rowmap(const int* __restrict__ texts, const int* __restrict__ lengths)
{
    int bs = blockIdx.x;
    int len = lengths[bs];
    int off = g_segoff[bs];
    int s = threadIdx.x;
    if (s < len) g_tokmap[off + s] = texts[bs * 128 + s];
}

// ---------------- weight preconversion: [Wf;Wb] -> tf32 hi/lo, bias sum ----------------
__global__ void k_convW(const float* __restrict__ Wf, const float* __restrict__ Wb,
                        const float* __restrict__ b1f, const float* __restrict__ b2f,
                        const float* __restrict__ b1b, const float* __restrict__ b2b)
{
    int idx = blockIdx.x * 256 + threadIdx.x;
#pragma unroll
    for (int e = 0; e < 4; e++) {
        int i = idx * 4 + e;
        int n = i >> 8, k = i & 255;
        float v = (n < 512) ? Wf[n * 256 + k] : Wb[(n - 512) * 256 + k];
        float hi = f2tf(v);
        g_Whi[i] = hi;
        g_Wlo[i] = f2tf(v - hi);
    }
    if (idx < 1024) {
        g_bias[idx] = (idx < 512) ? (b1f[idx] + b2f[idx])
                                  : (b1b[idx - 512] + b2b[idx - 512]);
    }
}

// ---------------- 3xTF32 tensor-core GEMM, preconverted weights ----------------
#define SMEM_G3 ((4 * 128 * 40 + 16 * 136) * 4)

template<int GATHER>
__global__ __launch_bounds__(256, 2) void k_gemm3(
    const float* __restrict__ A, float* __restrict__ C)
{
    int total = g_segoff[256];
    int bm = blockIdx.x * 128;
    if (bm >= total) return;
    int bn = blockIdx.y * 128;

    extern __shared__ float sm[];
    float* Ash = sm;                       // [128][40]
    float* Asl = sm + 128 * 40;
    float* Bsh = sm + 2 * 128 * 40;
    float* Bsl = sm + 3 * 128 * 40;
    float* bias_s = sm + 4 * 128 * 40;     // [16][136]

    int tid = threadIdx.x;
    for (int i = tid; i < 16 * 128; i += 256) {
        int r = i >> 7, c = i & 127;
        bias_s[r * 136 + c] = g_bias[bn + c];
    }

    int r0 = tid >> 3;
    int f4 = (tid & 7) * 4;
    const float* arow[4];
#pragma unroll
    for (int p = 0; p < 4; p++) {
        int pr = bm + r0 + 32 * p;
        if (GATHER) {
            int tok = (pr < total) ? g_tokmap[pr] : 0;
            arow[p] = A + (size_t)tok * 256;
        } else {
            arow[p] = A + (size_t)pr * 256;
        }
    }
    const float* whrow = g_Whi + (size_t)(bn + r0) * 256;
    const float* wlrow = g_Wlo + (size_t)(bn + r0) * 256;

    int wid = tid >> 5;
    int lm = (wid & 3) * 32;
    int ln = (wid >> 2) * 64;

    wmma::fragment<wmma::accumulator, 16, 16, 8, float> acc[2][4];
    __syncthreads();
#pragma unroll
    for (int mi = 0; mi < 2; mi++)
#pragma unroll
        for (int ni = 0; ni < 4; ni++)
            wmma::load_matrix_sync(acc[mi][ni], bias_s + ln + ni * 16, 136,
                                   wmma::mem_row_major);

    for (int k0 = 0; k0 < 256; k0 += 32) {
        float4 av[4], bh4[4], bl4[4];
#pragma unroll
        for (int p = 0; p < 4; p++) {
            av[p]  = *(const float4*)(arow[p] + k0 + f4);
            bh4[p] = *(const float4*)(whrow + (size_t)p * 32 * 256 + k0 + f4);
            bl4[p] = *(const float4*)(wlrow + (size_t)p * 32 * 256 + k0 + f4);
        }
        __syncthreads();
#pragma unroll
        for (int p = 0; p < 4; p++) {
            int row = (r0 + 32 * p) * 40 + f4;
            float h0 = f2tf(av[p].x), h1 = f2tf(av[p].y),
                  h2 = f2tf(av[p].z), h3 = f2tf(av[p].w);
            *(float4*)&Ash[row] = make_float4(h0, h1, h2, h3);
            *(float4*)&Asl[row] = make_float4(f2tf(av[p].x - h0), f2tf(av[p].y - h1),
                                              f2tf(av[p].z - h2), f2tf(av[p].w - h3));
            *(float4*)&Bsh[row] = bh4[p];
            *(float4*)&Bsl[row] = bl4[p];
        }
        __syncthreads();
#pragma unroll
        for (int ks = 0; ks < 4; ks++) {
            wmma::fragment<wmma::matrix_a, 16, 16, 8, wmma::precision::tf32,
                           wmma::row_major> ah[2], al[2];
#pragma unroll
            for (int mi = 0; mi < 2; mi++) {
                wmma::load_matrix_sync(ah[mi], Ash + (lm + mi * 16) * 40 + ks * 8, 40);
                wmma::load_matrix_sync(al[mi], Asl + (lm + mi * 16) * 40 + ks * 8, 40);
            }
#pragma unroll
            for (int ni = 0; ni < 4; ni++) {
                wmma::fragment<wmma::matrix_b, 16, 16, 8, wmma::precision::tf32,
                               wmma::col_major> bh, bl;
                wmma::load_matrix_sync(bh, Bsh + (ln + ni * 16) * 40 + ks * 8, 40);
                wmma::load_matrix_sync(bl, Bsl + (ln + ni * 16) * 40 + ks * 8, 40);
#pragma unroll
                for (int mi = 0; mi < 2; mi++) {
                    wmma::mma_sync(acc[mi][ni], ah[mi], bl, acc[mi][ni]);
                    wmma::mma_sync(acc[mi][ni], al[mi], bh, acc[mi][ni]);
                    wmma::mma_sync(acc[mi][ni], ah[mi], bh, acc[mi][ni]);
                }
            }
        }
    }
#pragma unroll
    for (int mi = 0; mi < 2; mi++)
#pragma unroll
        for (int ni = 0; ni < 4; ni++)
            wmma::store_matrix_sync(
                C + (size_t)(bm + lm + mi * 16) * 1024 + bn + ln + ni * 16,
                acc[mi][ni], 1024, wmma::mem_row_major);
}

// ---------------- unified cluster LSTM core ----------------
// 2 CTAs per (sequence, direction). CTA rank r owns gate rows [r*256, r*256+256),
// 2 threads per row, 64 weights each in registers. Per step: gates -> STS local +
// st.shared::cluster to peer (parity double-buffered) -> __syncwarp -> lane0-elected
// mbarrier arrive (local + remote release; 32 arrivals/phase total) -> t<128 waits,
// runs the replicated c/h update (h stays CTA-local), rank 0 stores output.
__device__ __forceinline__ void lstm_cc(
    const float* __restrict__ Whh,      // 512 x 128 for this direction
    const float* __restrict__ Gbase,    // xgate base (+grow per-thread inside)
    float* __restrict__ Obase,          // output row base (+t inside)
    int len, int reverse, unsigned rank, int t,
    float (*ga)[512], float* hs, unsigned long long* mbar_store,
    float c_init, int write_final, int dir, int b)
{
    int row  = t >> 1, half = t & 1;
    int grow = (int)rank * 256 + row;   // global gate row 0..511

    unsigned long long w2[32];          // 64 weights packed in pairs
    const float4* wr = (const float4*)(Whh + (size_t)grow * 128 + half * 64);
#pragma unroll
    for (int q = 0; q < 16; q++) {
        float4 v = wr[q];
        w2[2*q]   = pk2(v.x, v.y);
        w2[2*q+1] = pk2(v.z, v.w);
    }

    unsigned bar      = smem_u32(mbar_store);
    unsigned peer_bar = mapa_u32(bar, rank ^ 1);
    unsigned ga_u32   = smem_u32(&ga[0][0]);
    unsigned peer_ga  = mapa_u32(ga_u32 + (unsigned)grow * 4, rank ^ 1);

    float c = c_init;
    if (t == 0) mbar_init(bar, 32);     // 16 local + 16 remote elected arrivals
    __syncthreads();
    cluster_sync_();                    // mbar + hs visible cluster-wide

    int stp = reverse ? -1 : 1;
    int s   = reverse ? (len - 1) : 0;
    const float* Gp = Gbase + grow;
    float xg = (half == 0) ? Gp[(size_t)s * 1024] : 0.f;
    bool isg = (rank == 1) && (row < 128);      // g-gate rows 256..383

    for (int it = 0; it < len; it++) {
        int p = it & 1;
        float xgn = 0.f;
        if (half == 0 && it + 1 < len) xgn = Gp[(size_t)(s + stp) * 1024];

        unsigned long long A = pk2(xg, 0.f), B = pk2(0.f, 0.f);
        const ulonglong2* h2 = (const ulonglong2*)(hs + half * 64);
#pragma unroll
        for (int q = 0; q < 16; q++) {
            ulonglong2 hv = h2[q];
            A = ffma2(w2[2*q],   hv.x, A);
            B = ffma2(w2[2*q+1], hv.y, B);
        }
        float alo, ahi, blo, bhi;
        unpk2(A, alo, ahi); unpk2(B, blo, bhi);
        float part = (alo + blo) + (ahi + bhi);
        float tot  = part + __shfl_xor_sync(0xFFFFFFFFu, part, 1);
        if (half == 0) {
            float act = isg ? tanh_fast(tot) : sig_fast(tot);
            ga[p][grow] = act;
            st_shared_cluster_f32(peer_ga + (unsigned)p * 2048, act);
        }
        __syncwarp();
        if ((t & 31) == 0) {            // elected arrivals: orders the whole warp's
            mbar_arrive_local(bar);     // stores (syncwarp) before the release
            mbar_arrive_remote(peer_bar);
        }
        if (t < 128) {
            mbar_wait_cluster(bar, (unsigned)p);
            float iv = ga[p][t], fv = ga[p][128 + t], gv = ga[p][256 + t], ov = ga[p][384 + t];
            c = fmaf(fv, c, iv * gv);
            float hn = ov * tanh_fast(c);
            hs[t] = hn;
            if (rank == 0) Obase[(size_t)s * 256 + t] = hn;
        }
        __syncthreads();
        s += stp;
        xg = xgn;
    }
    if (write_final && rank == 0 && t < 128) {
        g_Hf[dir][b][t] = hs[t];
        g_Cf[dir][b][t] = c;
    }
    cluster_sync_();                    // no early exit while peer still sends
}

__global__ __launch_bounds__(512, 1) __cluster_dims__(2, 1, 1)
void k_lstm1c(const int* __restrict__ lengths,
              const float* __restrict__ Whh_f, const float* __restrict__ Whh_b)
{
    __shared__ float ga[2][512];
    __shared__ float hs[128];
    __shared__ __align__(8) unsigned long long mbar_store;
    unsigned rank;
    asm("mov.u32 %0, %%cluster_ctarank;" : "=r"(rank));
    int t   = threadIdx.x;
    int cid = blockIdx.x >> 1;          // 0..511 : dir*256 + bs
    int dir = cid >> 8;
    int bs  = cid & 255;
    int len = lengths[bs];
    int off = g_segoff[bs];
    if (t < 128) hs[t] = 0.f;
    lstm_cc(dir ? Whh_b : Whh_f,
            g_G1 + (size_t)off * 1024 + dir * 512,
            g_P2 + (size_t)off * 256 + dir * 128,
            len, dir, rank, t, ga, hs, &mbar_store,
            0.f, (bs & 7) == 7, dir, bs >> 3);
}

__global__ __launch_bounds__(512, 1) __cluster_dims__(2, 1, 1)
void k_lstm2c(const float* __restrict__ Whh_f, const float* __restrict__ Whh_b)
{
    __shared__ float ga[2][512];
    __shared__ float hs[128];
    __shared__ __align__(8) unsigned long long mbar_store;
    unsigned rank;
    asm("mov.u32 %0, %%cluster_ctarank;" : "=r"(rank));
    int t   = threadIdx.x;
    int cid = blockIdx.x >> 1;          // dir*32 + b
    int dir = cid >> 5;
    int b   = cid & 31;
    int base = g_segoff[b * 8];
    int len  = g_segoff[b * 8 + 8] - base;
    float ci = 0.f;
    if (t < 128) { hs[t] = g_Hf[dir][b][t]; ci = g_Cf[dir][b][t]; }
    lstm_cc(dir ? Whh_b : Whh_f,
            g_G2 + (size_t)base * 1024 + dir * 512,
            g_OUT2 + (size_t)base * 256 + dir * 128,
            len, dir, rank, t, ga, hs, &mbar_store,
            ci, 0, dir, b);
}

// ---------------- emission: warp per packed row ----------------
__global__ void k_emission(const float* __restrict__ Wlin, const float* __restrict__ blin)
{
    int total = g_segoff[256];
    int gw   = (blockIdx.x * blockDim.x + threadIdx.x) >> 5;
    int nw   = (gridDim.x * blockDim.x) >> 5;
    int lane = threadIdx.x & 31;
    int k = lane & 15, half = lane >> 4;
    const float4* wr = (const float4*)(Wlin + k * 256 + half * 128);
    float4 wreg[32];
#pragma unroll
    for (int q = 0; q < 32; q++) wreg[q] = wr[q];
    float bk = blin[k];
    for (int r = gw; r < total; r += nw) {
        const float4* xr = (const float4*)(g_OUT2 + (size_t)r * 256 + half * 128);
        float a = 0.f;
#pragma unroll
        for (int q = 0; q < 32; q++) {
            float4 x = xr[q], wv = wreg[q];
            a = fmaf(x.x, wv.x, a); a = fmaf(x.y, wv.y, a);
            a = fmaf(x.z, wv.z, a); a = fmaf(x.w, wv.w, a);
        }
        a += __shfl_xor_sync(0xFFFFFFFFu, a, 16);
        if (lane < 16) g_EM[(size_t)r * 16 + k] = a + bk;
    }
}

// ---------------- Viterbi: one block per batch, smem history ----------------
__global__ __launch_bounds__(32, 1) void k_viterbi(
    const float* __restrict__ startv, const float* __restrict__ trans,
    const float* __restrict__ endv, float* __restrict__ out)
{
    __shared__ unsigned char hist[(TTOT - 1) * 16];
    int b    = blockIdx.x;
    int lane = threadIdx.x;
    int j    = lane & 15;
    int base = g_segoff[b * 8];
    int L    = g_segoff[b * 8 + 8] - base;
    float trC[16];
#pragma unroll
    for (int i = 0; i < 16; i++) trC[i] = trans[i * 16 + j];
    const float* em = g_EM + (size_t)base * 16;

    float sc  = startv[j] + em[j];
    float emj = em[16 + j];
    for (int t = 1; t < L; t++) {
        float em_next = (t + 1 < L) ? em[(t + 1) * 16 + j] : 0.0f;
        float best = -3.4e38f; int bi = 0;
#pragma unroll
        for (int i = 0; i < 16; i++) {
            float v = (__shfl_sync(0xFFFFFFFFu, sc, i) + trC[i]) + emj;
            if (v > best) { best = v; bi = i; }
        }
        sc = best;
        if (lane < 16) hist[(t - 1) * 16 + j] = (unsigned char)bi;
        emj = em_next;
    }
    float fin = sc + endv[j];
    float bestv = -3.4e38f; int last = 0;
#pragma unroll
    for (int i = 0; i < 16; i++) {
        float v = __shfl_sync(0xFFFFFFFFu, fin, i);
        if (v > bestv) { bestv = v; last = i; }
    }
    __syncwarp();
    if (lane == 0) {
        out[32768 + b] = bestv;
        int cur = last;
        out[(TTOT - 1) * 32 + b] = (float)cur;
        for (int t = TTOT - 1; t >= L; t--) out[(t - 1) * 32 + b] = (float)cur;
        for (int t = L - 1; t >= 1; t--) {
            cur = hist[(t - 1) * 16 + cur];
            out[(t - 1) * 32 + b] = (float)cur;
        }
    }
}

// ---------------- launch ----------------
extern "C" void kernel_launch(void* const* d_in, const int* in_sizes, int n_in,
                              void* d_out, int out_size)
{
    const int*   texts   = (const int*)  d_in[0];
    const int*   lengths = (const int*)  d_in[1];
    const float* emb     = (const float*)d_in[2];
    const float* Wih_f   = (const float*)d_in[3];
    const float* Whh_f   = (const float*)d_in[4];
    const float* bih_f   = (const float*)d_in[5];
    const float* bhh_f   = (const float*)d_in[6];
    const float* Wih_b   = (const float*)d_in[7];
    const float* Whh_b   = (const float*)d_in[8];
    const float* bih_b   = (const float*)d_in[9];
    const float* bhh_b   = (const float*)d_in[10];
    const float* Wlin    = (const float*)d_in[11];
    const float* blin    = (const float*)d_in[12];
    const float* crf_s   = (const float*)d_in[13];
    const float* crf_t   = (const float*)d_in[14];
    const float* crf_e   = (const float*)d_in[15];
    float* out = (float*)d_out;

    cudaFuncSetAttribute(k_gemm3<1>, cudaFuncAttributeMaxDynamicSharedMemorySize, SMEM_G3);
    cudaFuncSetAttribute(k_gemm3<0>, cudaFuncAttributeMaxDynamicSharedMemorySize, SMEM_G3);

    float *pG1, *pP2, *pG2;
    cudaGetSymbolAddress((void**)&pG1, g_G1);
    cudaGetSymbolAddress((void**)&pP2, g_P2);
    cudaGetSymbolAddress((void**)&pG2, g_G2);

    k_offsets<<<1, 32>>>(lengths);
    k_rowmap<<<256, 128>>>(texts, lengths);
    k_convW<<<256, 256>>>(Wih_f, Wih_b, bih_f, bhh_f, bih_b, bhh_b);
    k_gemm3<1><<<dim3(256, 8), 256, SMEM_G3>>>(emb, pG1);
    k_lstm1c<<<1024, 512>>>(lengths, Whh_f, Whh_b);
    k_gemm3<0><<<dim3(256, 8), 256, SMEM_G3>>>(pP2, pG2);
    k_lstm2c<<<128, 512>>>(Whh_f, Whh_b);
    k_emission<<<148, 256>>>(Wlin, blin);
    k_viterbi<<<32, 32>>>(crf_s, crf_t, crf_e, out);
}

// round 12
// speedup vs baseline: 1.1065x; 1.1065x over previous
#include <cuda_runtime.h>
#include <cstdint>
#include <mma.h>
#include <math.h>
using namespace nvcuda;

#define BATCH 32
#define NSEGC 8
#define SLEN  128
#define TTOT  1024
#define KTAG  16
#define MROWS 32768

// ---------------- device scratch ----------------
__device__ float g_G1 [(size_t)MROWS * 1024];   // stage1 x-gates (packed rows)
__device__ float g_P2 [(size_t)MROWS * 256];    // packed lstm2 input (= packed stage1 out)
__device__ float g_G2 [(size_t)MROWS * 1024];   // stage2 x-gates (packed rows)
__device__ float g_OUT2[(size_t)MROWS * 256];   // stage2 outputs (packed)
__device__ float g_EM [(size_t)MROWS * KTAG];   // emissions (packed)
__device__ float g_Whi[1024 * 256];             // tf32-hi of [Wf;Wb]
__device__ float g_Wlo[1024 * 256];             // tf32-lo of [Wf;Wb]
__device__ float g_bias[1024];                  // bih+bhh, f then b
__device__ int   g_segoff[257];
__device__ int   g_tokmap[MROWS];
__device__ float g_Hf[2][BATCH][128];
__device__ float g_Cf[2][BATCH][128];

// ---------------- helpers ----------------
__device__ __forceinline__ float f2tf(float x)
{
    float r;
    asm("cvt.rna.tf32.f32 %0, %1;" : "=f"(r) : "f"(x));
    return r;
}
__device__ __forceinline__ float sig_fast(float x)
{
    return __fdividef(1.0f, 1.0f + __expf(-x));
}
__device__ __forceinline__ float tanh_fast(float x)
{
    return 1.0f - 2.0f * __fdividef(1.0f, 1.0f + __expf(2.0f * x));
}
// packed fp32x2 FMA (Blackwell FFMA2; PTX-only form)
__device__ __forceinline__ unsigned long long ffma2(
    unsigned long long a, unsigned long long b, unsigned long long c)
{
    unsigned long long d;
    asm("fma.rn.f32x2 %0, %1, %2, %3;" : "=l"(d) : "l"(a), "l"(b), "l"(c));
    return d;
}
__device__ __forceinline__ unsigned long long pk2(float lo, float hi)
{
    unsigned long long r;
    asm("mov.b64 %0, {%1, %2};" : "=l"(r) : "f"(lo), "f"(hi));
    return r;
}
__device__ __forceinline__ void unpk2(unsigned long long v, float& lo, float& hi)
{
    asm("mov.b64 {%0, %1}, %2;" : "=f"(lo), "=f"(hi) : "l"(v));
}
__device__ __forceinline__ unsigned smem_u32(const void* p)
{
    return (unsigned)__cvta_generic_to_shared(p);
}
__device__ __forceinline__ unsigned mapa_u32(unsigned a, unsigned r)
{
    unsigned d;
    asm("mapa.shared::cluster.u32 %0, %1, %2;" : "=r"(d) : "r"(a), "r"(r));
    return d;
}
__device__ __forceinline__ void mbar_init(unsigned a, unsigned cnt)
{
    asm volatile("mbarrier.init.shared.b64 [%0], %1;" :: "r"(a), "r"(cnt) : "memory");
}
__device__ __forceinline__ void mbar_arrive_local(unsigned a)
{
    asm volatile("mbarrier.arrive.shared::cta.b64 _, [%0];" :: "r"(a) : "memory");
}
__device__ __forceinline__ void mbar_arrive_remote(unsigned a)
{
    asm volatile("mbarrier.arrive.release.cluster.shared::cluster.b64 _, [%0];"
                 :: "r"(a) : "memory");
}
__device__ __forceinline__ void mbar_wait_cluster(unsigned a, unsigned phase)
{
    asm volatile(
        "{\n\t"
        ".reg .pred P;\n\t"
        "WLOOP%=:\n\t"
        "mbarrier.try_wait.parity.acquire.cluster.shared::cta.b64 P, [%0], %1;\n\t"
        "@!P bra WLOOP%=;\n\t"
        "}"
        :: "r"(a), "r"(phase) : "memory");
}
__device__ __forceinline__ void st_shared_cluster_f32(unsigned a, float v)
{
    asm volatile("st.shared::cluster.f32 [%0], %1;" :: "r"(a), "f"(v) : "memory");
}
__device__ __forceinline__ void cluster_sync_()
{
    asm volatile("barrier.cluster.arrive.aligned;" ::: "memory");
    asm volatile("barrier.cluster.wait.aligned;" ::: "memory");
}

// ---------------- offsets: warp scan of 256 lengths ----------------
__global__ void k_offsets(const int* __restrict__ lengths)
{
    int lane = threadIdx.x;
    int v[8], s = 0;
#pragma unroll
    for (int i = 0; i < 8; i++) { v[i] = lengths[lane * 8 + i]; s += v[i]; }
    int inc = s;
#pragma unroll
    for (int d = 1; d < 32; d <<= 1) {
        int o = __shfl_up_sync(0xFFFFFFFFu, inc, d);
        if (lane >= d) inc += o;
    }
    int run = inc - s;                    // exclusive prefix of lane sums
#pragma unroll
    for (int i = 0; i < 8; i++) { g_segoff[lane * 8 + i] = run; run += v[i]; }
    if (lane == 31) g_segoff[256] = run;
}

__global__ void k_rowmap(const int* __restrict__ texts, const int* __restrict__ lengths)
{
    int bs = blockIdx.x;
    int len = lengths[bs];
    int off = g_segoff[bs];
    int s = threadIdx.x;
    if (s < len) g_tokmap[off + s] = texts[bs * 128 + s];
}

// ---------------- weight preconversion: [Wf;Wb] -> tf32 hi/lo, bias sum ----------------
__global__ void k_convW(const float* __restrict__ Wf, const float* __restrict__ Wb,
                        const float* __restrict__ b1f, const float* __restrict__ b2f,
                        const float* __restrict__ b1b, const float* __restrict__ b2b)
{
    int idx = blockIdx.x * 256 + threadIdx.x;
#pragma unroll
    for (int e = 0; e < 4; e++) {
        int i = idx * 4 + e;
        int n = i >> 8, k = i & 255;
        float v = (n < 512) ? Wf[n * 256 + k] : Wb[(n - 512) * 256 + k];
        float hi = f2tf(v);
        g_Whi[i] = hi;
        g_Wlo[i] = f2tf(v - hi);
    }
    if (idx < 1024) {
        g_bias[idx] = (idx < 512) ? (b1f[idx] + b2f[idx])
                                  : (b1b[idx - 512] + b2b[idx - 512]);
    }
}

// ---------------- 3xTF32 tensor-core GEMM, preconverted weights ----------------
#define SMEM_G3 ((4 * 128 * 40 + 16 * 136) * 4)

template<int GATHER>
__global__ __launch_bounds__(256, 2) void k_gemm3(
    const float* __restrict__ A, float* __restrict__ C)
{
    int total = g_segoff[256];
    int bm = blockIdx.x * 128;
    if (bm >= total) return;
    int bn = blockIdx.y * 128;

    extern __shared__ float sm[];
    float* Ash = sm;                       // [128][40]
    float* Asl = sm + 128 * 40;
    float* Bsh = sm + 2 * 128 * 40;
    float* Bsl = sm + 3 * 128 * 40;
    float* bias_s = sm + 4 * 128 * 40;     // [16][136]

    int tid = threadIdx.x;
    for (int i = tid; i < 16 * 128; i += 256) {
        int r = i >> 7, c = i & 127;
        bias_s[r * 136 + c] = g_bias[bn + c];
    }

    int r0 = tid >> 3;
    int f4 = (tid & 7) * 4;
    const float* arow[4];
#pragma unroll
    for (int p = 0; p < 4; p++) {
        int pr = bm + r0 + 32 * p;
        if (GATHER) {
            int tok = (pr < total) ? g_tokmap[pr] : 0;
            arow[p] = A + (size_t)tok * 256;
        } else {
            arow[p] = A + (size_t)pr * 256;
        }
    }
    const float* whrow = g_Whi + (size_t)(bn + r0) * 256;
    const float* wlrow = g_Wlo + (size_t)(bn + r0) * 256;

    int wid = tid >> 5;
    int lm = (wid & 3) * 32;
    int ln = (wid >> 2) * 64;

    wmma::fragment<wmma::accumulator, 16, 16, 8, float> acc[2][4];
    __syncthreads();
#pragma unroll
    for (int mi = 0; mi < 2; mi++)
#pragma unroll
        for (int ni = 0; ni < 4; ni++)
            wmma::load_matrix_sync(acc[mi][ni], bias_s + ln + ni * 16, 136,
                                   wmma::mem_row_major);

    for (int k0 = 0; k0 < 256; k0 += 32) {
        float4 av[4], bh4[4], bl4[4];
#pragma unroll
        for (int p = 0; p < 4; p++) {
            av[p]  = *(const float4*)(arow[p] + k0 + f4);
            bh4[p] = *(const float4*)(whrow + (size_t)p * 32 * 256 + k0 + f4);
            bl4[p] = *(const float4*)(wlrow + (size_t)p * 32 * 256 + k0 + f4);
        }
        __syncthreads();
#pragma unroll
        for (int p = 0; p < 4; p++) {
            int row = (r0 + 32 * p) * 40 + f4;
            float h0 = f2tf(av[p].x), h1 = f2tf(av[p].y),
                  h2 = f2tf(av[p].z), h3 = f2tf(av[p].w);
            *(float4*)&Ash[row] = make_float4(h0, h1, h2, h3);
            *(float4*)&Asl[row] = make_float4(f2tf(av[p].x - h0), f2tf(av[p].y - h1),
                                              f2tf(av[p].z - h2), f2tf(av[p].w - h3));
            *(float4*)&Bsh[row] = bh4[p];
            *(float4*)&Bsl[row] = bl4[p];
        }
        __syncthreads();
#pragma unroll
        for (int ks = 0; ks < 4; ks++) {
            wmma::fragment<wmma::matrix_a, 16, 16, 8, wmma::precision::tf32,
                           wmma::row_major> ah[2], al[2];
#pragma unroll
            for (int mi = 0; mi < 2; mi++) {
                wmma::load_matrix_sync(ah[mi], Ash + (lm + mi * 16) * 40 + ks * 8, 40);
                wmma::load_matrix_sync(al[mi], Asl + (lm + mi * 16) * 40 + ks * 8, 40);
            }
#pragma unroll
            for (int ni = 0; ni < 4; ni++) {
                wmma::fragment<wmma::matrix_b, 16, 16, 8, wmma::precision::tf32,
                               wmma::col_major> bh, bl;
                wmma::load_matrix_sync(bh, Bsh + (ln + ni * 16) * 40 + ks * 8, 40);
                wmma::load_matrix_sync(bl, Bsl + (ln + ni * 16) * 40 + ks * 8, 40);
#pragma unroll
                for (int mi = 0; mi < 2; mi++) {
                    wmma::mma_sync(acc[mi][ni], ah[mi], bl, acc[mi][ni]);
                    wmma::mma_sync(acc[mi][ni], al[mi], bh, acc[mi][ni]);
                    wmma::mma_sync(acc[mi][ni], ah[mi], bh, acc[mi][ni]);
                }
            }
        }
    }
#pragma unroll
    for (int mi = 0; mi < 2; mi++)
#pragma unroll
        for (int ni = 0; ni < 4; ni++)
            wmma::store_matrix_sync(
                C + (size_t)(bm + lm + mi * 16) * 1024 + bn + ln + ni * 16,
                acc[mi][ni], 1024, wmma::mem_row_major);
}

// ---------------- LSTM1 recurrent core (unpaired, FFMA2 gate matvec) ----------------
#define SMEM_LSTM ((512 * 68 + 128 + 512) * 4)

__device__ __forceinline__ void lstm_run(
    const float* __restrict__ Whh, const float* __restrict__ Gbase,
    float* __restrict__ Obase, int len, int dir, int t,
    float* ws, float* hs, float* ga,
    float h_init, float c_init, int write_final, int b)
{
    const float* wr = Whh + t * 128;
    unsigned long long w2[32];             // first 64 weights, packed pairs
#pragma unroll
    for (int q = 0; q < 16; q++) {
        float4 v = *(const float4*)(wr + q * 4);
        w2[2*q]   = pk2(v.x, v.y);
        w2[2*q+1] = pk2(v.z, v.w);
    }
    float* wsr = ws + t * 68;              // last 64 weights in smem (16B aligned)
#pragma unroll
    for (int q = 0; q < 16; q++)
        *(float4*)(wsr + 4 * q) = *(const float4*)(wr + 64 + 4 * q);

    float c = c_init;
    if (t < 128) hs[t] = h_init;
    __syncthreads();

    int s    = dir ? (len - 1) : 0;
    int step = dir ? -1 : 1;
    bool isg = ((t >> 7) == 2);
    float xg = Gbase[(size_t)s * 1024];
    for (int it = 0; it < len; it++) {
        int s_next = s + step;
        float xg_next = (it + 1 < len) ? Gbase[(size_t)s_next * 1024] : 0.0f;
        unsigned long long A = pk2(xg, 0.f), B = pk2(0.f, 0.f);
        const ulonglong2* h2 = (const ulonglong2*)hs;        // 128 floats = 32 u64
#pragma unroll
        for (int q = 0; q < 16; q++) {
            ulonglong2 hv = h2[q];
            A = ffma2(w2[2*q],   hv.x, A);
            B = ffma2(w2[2*q+1], hv.y, B);
        }
        const ulonglong2* w2s = (const ulonglong2*)wsr;
#pragma unroll
        for (int q = 0; q < 16; q++) {
            ulonglong2 wv = w2s[q];
            ulonglong2 hv = h2[16 + q];
            A = ffma2(wv.x, hv.x, A);
            B = ffma2(wv.y, hv.y, B);
        }
        float alo, ahi, blo, bhi;
        unpk2(A, alo, ahi); unpk2(B, blo, bhi);
        float acc = (alo + blo) + (ahi + bhi);
        ga[t] = isg ? tanh_fast(acc) : sig_fast(acc);
        __syncthreads();
        if (t < 128) {
            float iv = ga[t], fv = ga[128 + t], gv = ga[256 + t], ov = ga[384 + t];
            c = fmaf(fv, c, iv * gv);
            float hn = ov * tanh_fast(c);
            hs[t] = hn;
            Obase[(size_t)s * 256 + t] = hn;
        }
        __syncthreads();
        xg = xg_next;
        s  = s_next;
    }
    if (write_final && t < 128) {
        g_Hf[dir][b][t] = hs[t];
        g_Cf[dir][b][t] = c;
    }
}

__global__ __launch_bounds__(512, 1) void k_lstm1(
    const int* __restrict__ lengths,
    const float* __restrict__ Whh_f, const float* __restrict__ Whh_b)
{
    extern __shared__ float sm[];
    float* ws = sm;
    float* hs = sm + 512 * 68;
    float* ga = hs + 128;
    int t   = threadIdx.x;
    int blk = blockIdx.x;
    int dir = blk >> 8;
    int b   = (blk & 255) >> 3;
    int seg = blk & 7;
    int bs  = b * NSEGC + seg;
    int len = lengths[bs];
    int off = g_segoff[bs];
    const float* Gbase = g_G1 + (size_t)off * 1024 + dir * 512 + t;
    float* Obase = g_P2 + (size_t)off * 256 + dir * 128;
    lstm_run(dir ? Whh_b : Whh_f, Gbase, Obase, len, dir, t, ws, hs, ga,
             0.0f, 0.0f, (seg == NSEGC - 1), b);
}

// ---------------- LSTM2: 2-CTA cluster per (b,dir), reg weights + FFMA2 ----------
// Single change vs R9: ELECTED mbarrier arrivals. Producers store gates (local STS +
// st.shared::cluster to peer), then __syncwarp orders the whole warp's stores before
// lane 0's single local arrive + single remote release-arrive. Arrivals per phase:
// 512 -> 32 (16 local + 16 remote).
__global__ __launch_bounds__(512, 1) __cluster_dims__(2, 1, 1)
void k_lstm2c(const float* __restrict__ Whh_f, const float* __restrict__ Whh_b)
{
    __shared__ float ga[2][512];
    __shared__ float hs[128];
    __shared__ __align__(8) unsigned long long mbar_store;

    unsigned rank;
    asm("mov.u32 %0, %%cluster_ctarank;" : "=r"(rank));
    int t   = threadIdx.x;
    int cid = blockIdx.x >> 1;          // cluster index: dir*32 + b
    int dir = cid >> 5;
    int b   = cid & 31;

    int base = g_segoff[b * 8];
    int len  = g_segoff[b * 8 + 8] - base;

    int row  = t >> 1, half = t & 1;
    int grow = (int)rank * 256 + row;   // global gate row 0..511

    const float* Whh = dir ? Whh_b : Whh_f;
    unsigned long long w2[32];          // 64 weights packed
    const float4* wr = (const float4*)(Whh + (size_t)grow * 128 + half * 64);
#pragma unroll
    for (int q = 0; q < 16; q++) {
        float4 v = wr[q];
        w2[2*q]   = pk2(v.x, v.y);
        w2[2*q+1] = pk2(v.z, v.w);
    }

    unsigned bar      = smem_u32(&mbar_store);
    unsigned peer_bar = mapa_u32(bar, rank ^ 1);
    unsigned ga_u32   = smem_u32(&ga[0][0]);
    unsigned peer_ga  = mapa_u32(ga_u32 + (unsigned)grow * 4, rank ^ 1); // +p*2048 per step

    float c = 0.f;
    if (t < 128) { hs[t] = g_Hf[dir][b][t]; c = g_Cf[dir][b][t]; }
    if (t == 0) mbar_init(bar, 32);     // 16 local + 16 remote elected arrivals
    __syncthreads();
    cluster_sync_();                    // mbar + hs visible cluster-wide

    int stp = dir ? -1 : 1;
    int s   = dir ? (len - 1) : 0;
    const float* G = g_G2 + (size_t)base * 1024 + dir * 512 + grow;
    float xg = (half == 0) ? G[(size_t)s * 1024] : 0.f;
    bool isg = (rank == 1) && (row < 128);      // g-gate rows 256..383
    float* Orow = g_OUT2 + (size_t)base * 256 + dir * 128;

    for (int it = 0; it < len; it++) {
        int p = it & 1;
        float xgn = 0.f;
        if (half == 0 && it + 1 < len) xgn = G[(size_t)(s + stp) * 1024];

        unsigned long long A = pk2(xg, 0.f), B = pk2(0.f, 0.f);
        const ulonglong2* h2 = (const ulonglong2*)(hs + half * 64);
#pragma unroll
        for (int q = 0; q < 16; q++) {
            ulonglong2 hv = h2[q];
            A = ffma2(w2[2*q],   hv.x, A);
            B = ffma2(w2[2*q+1], hv.y, B);
        }
        float alo, ahi, blo, bhi;
        unpk2(A, alo, ahi); unpk2(B, blo, bhi);
        float part = (alo + blo) + (ahi + bhi);
        float tot  = part + __shfl_xor_sync(0xFFFFFFFFu, part, 1);
        if (half == 0) {
            float act = isg ? tanh_fast(tot) : sig_fast(tot);
            ga[p][grow] = act;
            st_shared_cluster_f32(peer_ga + (unsigned)p * 2048, act);
        }
        __syncwarp();
        if ((t & 31) == 0) {            // elected: lane0 arrives for its whole warp
            mbar_arrive_local(bar);
            mbar_arrive_remote(peer_bar);
        }
        if (t < 128) {
            mbar_wait_cluster(bar, (unsigned)p);
            float iv = ga[p][t], fv = ga[p][128 + t], gv = ga[p][256 + t], ov = ga[p][384 + t];
            c = fmaf(fv, c, iv * gv);
            float hn = ov * tanh_fast(c);
            hs[t] = hn;
            if (rank == 0) Orow[(size_t)s * 256 + t] = hn;
        }
        __syncthreads();
        s += stp;
        xg = xgn;
    }
    cluster_sync_();                    // lifetime: no early exit while peer sends
}

// ---------------- emission: warp per packed row ----------------
__global__ void k_emission(const float* __restrict__ Wlin, const float* __restrict__ blin)
{
    int total = g_segoff[256];
    int gw   = (blockIdx.x * blockDim.x + threadIdx.x) >> 5;
    int nw   = (gridDim.x * blockDim.x) >> 5;
    int lane = threadIdx.x & 31;
    int k = lane & 15, half = lane >> 4;
    const float4* wr = (const float4*)(Wlin + k * 256 + half * 128);
    float4 wreg[32];
#pragma unroll
    for (int q = 0; q < 32; q++) wreg[q] = wr[q];
    float bk = blin[k];
    for (int r = gw; r < total; r += nw) {
        const float4* xr = (const float4*)(g_OUT2 + (size_t)r * 256 + half * 128);
        float a = 0.f;
#pragma unroll
        for (int q = 0; q < 32; q++) {
            float4 x = xr[q], wv = wreg[q];
            a = fmaf(x.x, wv.x, a); a = fmaf(x.y, wv.y, a);
            a = fmaf(x.z, wv.z, a); a = fmaf(x.w, wv.w, a);
        }
        a += __shfl_xor_sync(0xFFFFFFFFu, a, 16);
        if (lane < 16) g_EM[(size_t)r * 16 + k] = a + bk;
    }
}

// ---------------- Viterbi: one block per batch, smem history ----------------
__global__ __launch_bounds__(32, 1) void k_viterbi(
    const float* __restrict__ startv, const float* __restrict__ trans,
    const float* __restrict__ endv, float* __restrict__ out)
{
    __shared__ unsigned char hist[(TTOT - 1) * 16];
    int b    = blockIdx.x;
    int lane = threadIdx.x;
    int j    = lane & 15;
    int base = g_segoff[b * 8];
    int L    = g_segoff[b * 8 + 8] - base;
    float trC[16];
#pragma unroll
    for (int i = 0; i < 16; i++) trC[i] = trans[i * 16 + j];
    const float* em = g_EM + (size_t)base * 16;

    float sc  = startv[j] + em[j];
    float emj = em[16 + j];
    for (int t = 1; t < L; t++) {
        float em_next = (t + 1 < L) ? em[(t + 1) * 16 + j] : 0.0f;
        float best = -3.4e38f; int bi = 0;
#pragma unroll
        for (int i = 0; i < 16; i++) {
            float v = (__shfl_sync(0xFFFFFFFFu, sc, i) + trC[i]) + emj;
            if (v > best) { best = v; bi = i; }
        }
        sc = best;
        if (lane < 16) hist[(t - 1) * 16 + j] = (unsigned char)bi;
        emj = em_next;
    }
    float fin = sc + endv[j];
    float bestv = -3.4e38f; int last = 0;
#pragma unroll
    for (int i = 0; i < 16; i++) {
        float v = __shfl_sync(0xFFFFFFFFu, fin, i);
        if (v > bestv) { bestv = v; last = i; }
    }
    __syncwarp();
    if (lane == 0) {
        out[32768 + b] = bestv;
        int cur = last;
        out[(TTOT - 1) * 32 + b] = (float)cur;
        for (int t = TTOT - 1; t >= L; t--) out[(t - 1) * 32 + b] = (float)cur;
        for (int t = L - 1; t >= 1; t--) {
            cur = hist[(t - 1) * 16 + cur];
            out[(t - 1) * 32 + b] = (float)cur;
        }
    }
}

// ---------------- launch ----------------
extern "C" void kernel_launch(void* const* d_in, const int* in_sizes, int n_in,
                              void* d_out, int out_size)
{
    const int*   texts   = (const int*)  d_in[0];
    const int*   lengths = (const int*)  d_in[1];
    const float* emb     = (const float*)d_in[2];
    const float* Wih_f   = (const float*)d_in[3];
    const float* Whh_f   = (const float*)d_in[4];
    const float* bih_f   = (const float*)d_in[5];
    const float* bhh_f   = (const float*)d_in[6];
    const float* Wih_b   = (const float*)d_in[7];
    const float* Whh_b   = (const float*)d_in[8];
    const float* bih_b   = (const float*)d_in[9];
    const float* bhh_b   = (const float*)d_in[10];
    const float* Wlin    = (const float*)d_in[11];
    const float* blin    = (const float*)d_in[12];
    const float* crf_s   = (const float*)d_in[13];
    const float* crf_t   = (const float*)d_in[14];
    const float* crf_e   = (const float*)d_in[15];
    float* out = (float*)d_out;

    cudaFuncSetAttribute(k_lstm1, cudaFuncAttributeMaxDynamicSharedMemorySize, SMEM_LSTM);
    cudaFuncSetAttribute(k_gemm3<1>, cudaFuncAttributeMaxDynamicSharedMemorySize, SMEM_G3);
    cudaFuncSetAttribute(k_gemm3<0>, cudaFuncAttributeMaxDynamicSharedMemorySize, SMEM_G3);

    float *pG1, *pP2, *pG2;
    cudaGetSymbolAddress((void**)&pG1, g_G1);
    cudaGetSymbolAddress((void**)&pP2, g_P2);
    cudaGetSymbolAddress((void**)&pG2, g_G2);

    k_offsets<<<1, 32>>>(lengths);
    k_rowmap<<<256, 128>>>(texts, lengths);
    k_convW<<<256, 256>>>(Wih_f, Wih_b, bih_f, bhh_f, bih_b, bhh_b);
    k_gemm3<1><<<dim3(256, 8), 256, SMEM_G3>>>(emb, pG1);
    k_lstm1<<<512, 512, SMEM_LSTM>>>(lengths, Whh_f, Whh_b);
    k_gemm3<0><<<dim3(256, 8), 256, SMEM_G3>>>(pP2, pG2);
    k_lstm2c<<<128, 512>>>(Whh_f, Whh_b);
    k_emission<<<148, 256>>>(Wlin, blin);
    k_viterbi<<<32, 32>>>(crf_s, crf_t, crf_e, out);
}

// round 13
// speedup vs baseline: 1.1523x; 1.0414x over previous
#include <cuda_runtime.h>
#include <cstdint>
#include <mma.h>
#include <math.h>
using namespace nvcuda;

#define BATCH 32
#define NSEGC 8
#define SLEN  128
#define TTOT  1024
#define KTAG  16
#define MROWS 32768

// ---------------- device scratch ----------------
__device__ float g_G1 [(size_t)MROWS * 1024];   // stage1 x-gates (packed rows)
__device__ float g_P2 [(size_t)MROWS * 256];    // packed lstm2 input (= packed stage1 out)
__device__ float g_G2 [(size_t)MROWS * 1024];   // stage2 x-gates (packed rows)
__device__ float g_OUT2[(size_t)MROWS * 256];   // stage2 outputs (packed)
__device__ float g_EM [(size_t)MROWS * KTAG];   // emissions (packed)
__device__ float g_Whi[1024 * 256];             // tf32-hi of [Wf;Wb]
__device__ float g_Wlo[1024 * 256];             // tf32-lo of [Wf;Wb]
__device__ float g_bias[1024];                  // bih+bhh, f then b
__device__ int   g_segoff[257];
__device__ int   g_order[256];                  // segments sorted by descending length
__device__ int   g_tokmap[MROWS];
__device__ float g_Hf[2][BATCH][128];
__device__ float g_Cf[2][BATCH][128];

// ---------------- helpers ----------------
__device__ __forceinline__ float f2tf(float x)
{
    float r;
    asm("cvt.rna.tf32.f32 %0, %1;" : "=f"(r) : "f"(x));
    return r;
}
__device__ __forceinline__ float sig_fast(float x)
{
    return __fdividef(1.0f, 1.0f + __expf(-x));
}
__device__ __forceinline__ float tanh_fast(float x)
{
    return 1.0f - 2.0f * __fdividef(1.0f, 1.0f + __expf(2.0f * x));
}
// packed fp32x2 FMA (Blackwell FFMA2; PTX-only form)
__device__ __forceinline__ unsigned long long ffma2(
    unsigned long long a, unsigned long long b, unsigned long long c)
{
    unsigned long long d;
    asm("fma.rn.f32x2 %0, %1, %2, %3;" : "=l"(d) : "l"(a), "l"(b), "l"(c));
    return d;
}
__device__ __forceinline__ unsigned long long pk2(float lo, float hi)
{
    unsigned long long r;
    asm("mov.b64 %0, {%1, %2};" : "=l"(r) : "f"(lo), "f"(hi));
    return r;
}
__device__ __forceinline__ void unpk2(unsigned long long v, float& lo, float& hi)
{
    asm("mov.b64 {%0, %1}, %2;" : "=f"(lo), "=f"(hi) : "l"(v));
}
__device__ __forceinline__ unsigned smem_u32(const void* p)
{
    return (unsigned)__cvta_generic_to_shared(p);
}
__device__ __forceinline__ unsigned mapa_u32(unsigned a, unsigned r)
{
    unsigned d;
    asm("mapa.shared::cluster.u32 %0, %1, %2;" : "=r"(d) : "r"(a), "r"(r));
    return d;
}
__device__ __forceinline__ void mbar_init(unsigned a, unsigned cnt)
{
    asm volatile("mbarrier.init.shared.b64 [%0], %1;" :: "r"(a), "r"(cnt) : "memory");
}
__device__ __forceinline__ void mbar_arrive_local(unsigned a)
{
    asm volatile("mbarrier.arrive.shared::cta.b64 _, [%0];" :: "r"(a) : "memory");
}
__device__ __forceinline__ void mbar_arrive_remote(unsigned a)
{
    asm volatile("mbarrier.arrive.release.cluster.shared::cluster.b64 _, [%0];"
                 :: "r"(a) : "memory");
}
__device__ __forceinline__ void mbar_wait_cluster(unsigned a, unsigned phase)
{
    asm volatile(
        "{\n\t"
        ".reg .pred P;\n\t"
        "WLOOP%=:\n\t"
        "mbarrier.try_wait.parity.acquire.cluster.shared::cta.b64 P, [%0], %1;\n\t"
        "@!P bra WLOOP%=;\n\t"
        "}"
        :: "r"(a), "r"(phase) : "memory");
}
__device__ __forceinline__ void st_shared_cluster_f32(unsigned a, float v)
{
    asm volatile("st.shared::cluster.f32 [%0], %1;" :: "r"(a), "f"(v) : "memory");
}
__device__ __forceinline__ void cluster_sync_()
{
    asm volatile("barrier.cluster.arrive.aligned;" ::: "memory");
    asm volatile("barrier.cluster.wait.aligned;" ::: "memory");
}

// ---------------- prep: offsets + length sort + weight preconversion ----------------
// blocks 0..255: convert [Wf;Wb] -> tf32 hi/lo (+ bias sums on blocks 0..3)
// block 256: prefix offsets of the 256 segment lengths + descending-length order
__global__ void k_prep(const float* __restrict__ Wf, const float* __restrict__ Wb,
                       const float* __restrict__ b1f, const float* __restrict__ b2f,
                       const float* __restrict__ b1b, const float* __restrict__ b2b,
                       const int* __restrict__ lengths)
{
    if (blockIdx.x == 256) {
        __shared__ int slen[256];
        int t = threadIdx.x;
        slen[t] = lengths[t];
        __syncthreads();
        if (t < 32) {
            int v[8], s = 0;
#pragma unroll
            for (int i = 0; i < 8; i++) { v[i] = slen[t * 8 + i]; s += v[i]; }
            int inc = s;
#pragma unroll
            for (int d = 1; d < 32; d <<= 1) {
                int o = __shfl_up_sync(0xFFFFFFFFu, inc, d);
                if (t >= d) inc += o;
            }
            int run = inc - s;
#pragma unroll
            for (int i = 0; i < 8; i++) { g_segoff[t * 8 + i] = run; run += v[i]; }
            if (t == 31) g_segoff[256] = run;
        }
        // descending-length rank (ties by index) -> g_order[rank] = segment
        int li = slen[t];
        int rank = 0;
#pragma unroll 8
        for (int j = 0; j < 256; j++) {
            int lj = slen[j];
            rank += (lj > li) || (lj == li && j < t);
        }
        g_order[rank] = t;
        return;
    }
    int idx = blockIdx.x * 256 + threadIdx.x;
#pragma unroll
    for (int e = 0; e < 4; e++) {
        int i = idx * 4 + e;
        int n = i >> 8, k = i & 255;
        float v = (n < 512) ? Wf[n * 256 + k] : Wb[(n - 512) * 256 + k];
        float hi = f2tf(v);
        g_Whi[i] = hi;
        g_Wlo[i] = f2tf(v - hi);
    }
    if (idx < 1024) {
        g_bias[idx] = (idx < 512) ? (b1f[idx] + b2f[idx])
                                  : (b1b[idx - 512] + b2b[idx - 512]);
    }
}

__global__ void k_rowmap(const int* __restrict__ texts, const int* __restrict__ lengths)
{
    int bs = blockIdx.x;
    int len = lengths[bs];
    int off = g_segoff[bs];
    int s = threadIdx.x;
    if (s < len) g_tokmap[off + s] = texts[bs * 128 + s];
}

// ---------------- 3xTF32 tensor-core GEMM, preconverted weights ----------------
#define SMEM_G3 ((4 * 128 * 40 + 16 * 136) * 4)

template<int GATHER>
__global__ __launch_bounds__(256, 2) void k_gemm3(
    const float* __restrict__ A, float* __restrict__ C)
{
    int total = g_segoff[256];
    int bm = blockIdx.x * 128;
    if (bm >= total) return;
    int bn = blockIdx.y * 128;

    extern __shared__ float sm[];
    float* Ash = sm;                       // [128][40]
    float* Asl = sm + 128 * 40;
    float* Bsh = sm + 2 * 128 * 40;
    float* Bsl = sm + 3 * 128 * 40;
    float* bias_s = sm + 4 * 128 * 40;     // [16][136]

    int tid = threadIdx.x;
    for (int i = tid; i < 16 * 128; i += 256) {
        int r = i >> 7, c = i & 127;
        bias_s[r * 136 + c] = g_bias[bn + c];
    }

    int r0 = tid >> 3;
    int f4 = (tid & 7) * 4;
    const float* arow[4];
#pragma unroll
    for (int p = 0; p < 4; p++) {
        int pr = bm + r0 + 32 * p;
        if (GATHER) {
            int tok = (pr < total) ? g_tokmap[pr] : 0;
            arow[p] = A + (size_t)tok * 256;
        } else {
            arow[p] = A + (size_t)pr * 256;
        }
    }
    const float* whrow = g_Whi + (size_t)(bn + r0) * 256;
    const float* wlrow = g_Wlo + (size_t)(bn + r0) * 256;

    int wid = tid >> 5;
    int lm = (wid & 3) * 32;
    int ln = (wid >> 2) * 64;

    wmma::fragment<wmma::accumulator, 16, 16, 8, float> acc[2][4];
    __syncthreads();
#pragma unroll
    for (int mi = 0; mi < 2; mi++)
#pragma unroll
        for (int ni = 0; ni < 4; ni++)
            wmma::load_matrix_sync(acc[mi][ni], bias_s + ln + ni * 16, 136,
                                   wmma::mem_row_major);

    for (int k0 = 0; k0 < 256; k0 += 32) {
        float4 av[4], bh4[4], bl4[4];
#pragma unroll
        for (int p = 0; p < 4; p++) {
            av[p]  = *(const float4*)(arow[p] + k0 + f4);
            bh4[p] = *(const float4*)(whrow + (size_t)p * 32 * 256 + k0 + f4);
            bl4[p] = *(const float4*)(wlrow + (size_t)p * 32 * 256 + k0 + f4);
        }
        __syncthreads();
#pragma unroll
        for (int p = 0; p < 4; p++) {
            int row = (r0 + 32 * p) * 40 + f4;
            float h0 = f2tf(av[p].x), h1 = f2tf(av[p].y),
                  h2 = f2tf(av[p].z), h3 = f2tf(av[p].w);
            *(float4*)&Ash[row] = make_float4(h0, h1, h2, h3);
            *(float4*)&Asl[row] = make_float4(f2tf(av[p].x - h0), f2tf(av[p].y - h1),
                                              f2tf(av[p].z - h2), f2tf(av[p].w - h3));
            *(float4*)&Bsh[row] = bh4[p];
            *(float4*)&Bsl[row] = bl4[p];
        }
        __syncthreads();
#pragma unroll
        for (int ks = 0; ks < 4; ks++) {
            wmma::fragment<wmma::matrix_a, 16, 16, 8, wmma::precision::tf32,
                           wmma::row_major> ah[2], al[2];
#pragma unroll
            for (int mi = 0; mi < 2; mi++) {
                wmma::load_matrix_sync(ah[mi], Ash + (lm + mi * 16) * 40 + ks * 8, 40);
                wmma::load_matrix_sync(al[mi], Asl + (lm + mi * 16) * 40 + ks * 8, 40);
            }
#pragma unroll
            for (int ni = 0; ni < 4; ni++) {
                wmma::fragment<wmma::matrix_b, 16, 16, 8, wmma::precision::tf32,
                               wmma::col_major> bh, bl;
                wmma::load_matrix_sync(bh, Bsh + (ln + ni * 16) * 40 + ks * 8, 40);
                wmma::load_matrix_sync(bl, Bsl + (ln + ni * 16) * 40 + ks * 8, 40);
#pragma unroll
                for (int mi = 0; mi < 2; mi++) {
                    wmma::mma_sync(acc[mi][ni], ah[mi], bl, acc[mi][ni]);
                    wmma::mma_sync(acc[mi][ni], al[mi], bh, acc[mi][ni]);
                    wmma::mma_sync(acc[mi][ni], ah[mi], bh, acc[mi][ni]);
                }
            }
        }
    }
#pragma unroll
    for (int mi = 0; mi < 2; mi++)
#pragma unroll
        for (int ni = 0; ni < 4; ni++)
            wmma::store_matrix_sync(
                C + (size_t)(bm + lm + mi * 16) * 1024 + bn + ln + ni * 16,
                acc[mi][ni], 1024, wmma::mem_row_major);
}

// ---------------- LSTM1 recurrent core (unpaired, FFMA2 gate matvec) ----------------
#define SMEM_LSTM ((512 * 68 + 128 + 512) * 4)

__device__ __forceinline__ void lstm_run(
    const float* __restrict__ Whh, const float* __restrict__ Gbase,
    float* __restrict__ Obase, int len, int dir, int t,
    float* ws, float* hs, float* ga,
    float h_init, float c_init, int write_final, int b)
{
    const float* wr = Whh + t * 128;
    unsigned long long w2[32];             // first 64 weights, packed pairs
#pragma unroll
    for (int q = 0; q < 16; q++) {
        float4 v = *(const float4*)(wr + q * 4);
        w2[2*q]   = pk2(v.x, v.y);
        w2[2*q+1] = pk2(v.z, v.w);
    }
    float* wsr = ws + t * 68;              // last 64 weights in smem (16B aligned)
#pragma unroll
    for (int q = 0; q < 16; q++)
        *(float4*)(wsr + 4 * q) = *(const float4*)(wr + 64 + 4 * q);

    float c = c_init;
    if (t < 128) hs[t] = h_init;
    __syncthreads();

    int s    = dir ? (len - 1) : 0;
    int step = dir ? -1 : 1;
    bool isg = ((t >> 7) == 2);
    float xg = Gbase[(size_t)s * 1024];
    for (int it = 0; it < len; it++) {
        int s_next = s + step;
        float xg_next = (it + 1 < len) ? Gbase[(size_t)s_next * 1024] : 0.0f;
        unsigned long long A = pk2(xg, 0.f), B = pk2(0.f, 0.f);
        const ulonglong2* h2 = (const ulonglong2*)hs;        // 128 floats = 32 u64
#pragma unroll
        for (int q = 0; q < 16; q++) {
            ulonglong2 hv = h2[q];
            A = ffma2(w2[2*q],   hv.x, A);
            B = ffma2(w2[2*q+1], hv.y, B);
        }
        const ulonglong2* w2s = (const ulonglong2*)wsr;
#pragma unroll
        for (int q = 0; q < 16; q++) {
            ulonglong2 wv = w2s[q];
            ulonglong2 hv = h2[16 + q];
            A = ffma2(wv.x, hv.x, A);
            B = ffma2(wv.y, hv.y, B);
        }
        float alo, ahi, blo, bhi;
        unpk2(A, alo, ahi); unpk2(B, blo, bhi);
        float acc = (alo + blo) + (ahi + bhi);
        ga[t] = isg ? tanh_fast(acc) : sig_fast(acc);
        __syncthreads();
        if (t < 128) {
            float iv = ga[t], fv = ga[128 + t], gv = ga[256 + t], ov = ga[384 + t];
            c = fmaf(fv, c, iv * gv);
            float hn = ov * tanh_fast(c);
            hs[t] = hn;
            Obase[(size_t)s * 256 + t] = hn;
        }
        __syncthreads();
        xg = xg_next;
        s  = s_next;
    }
    if (write_final && t < 128) {
        g_Hf[dir][b][t] = hs[t];
        g_Cf[dir][b][t] = c;
    }
}

__global__ __launch_bounds__(512, 1) void k_lstm1(
    const int* __restrict__ lengths,
    const float* __restrict__ Whh_f, const float* __restrict__ Whh_b)
{
    extern __shared__ float sm[];
    float* ws = sm;
    float* hs = sm + 512 * 68;
    float* ga = hs + 128;
    int t   = threadIdx.x;
    int blk = blockIdx.x;
    int dir = blk >> 8;
    int bs  = g_order[blk & 255];          // LPT: longest segments first
    int len = lengths[bs];
    int off = g_segoff[bs];
    const float* Gbase = g_G1 + (size_t)off * 1024 + dir * 512 + t;
    float* Obase = g_P2 + (size_t)off * 256 + dir * 128;
    lstm_run(dir ? Whh_b : Whh_f, Gbase, Obase, len, dir, t, ws, hs, ga,
             0.0f, 0.0f, (bs & 7) == 7, bs >> 3);
}

// ---------------- LSTM2: 2-CTA cluster per (b,dir), reg weights + FFMA2 ----------
// Elected mbarrier arrivals (32/phase).
__global__ __launch_bounds__(512, 1) __cluster_dims__(2, 1, 1)
void k_lstm2c(const float* __restrict__ Whh_f, const float* __restrict__ Whh_b)
{
    __shared__ float ga[2][512];
    __shared__ float hs[128];
    __shared__ __align__(8) unsigned long long mbar_store;

    unsigned rank;
    asm("mov.u32 %0, %%cluster_ctarank;" : "=r"(rank));
    int t   = threadIdx.x;
    int cid = blockIdx.x >> 1;          // cluster index: dir*32 + b
    int dir = cid >> 5;
    int b   = cid & 31;

    int base = g_segoff[b * 8];
    int len  = g_segoff[b * 8 + 8] - base;

    int row  = t >> 1, half = t & 1;
    int grow = (int)rank * 256 + row;   // global gate row 0..511

    const float* Whh = dir ? Whh_b : Whh_f;
    unsigned long long w2[32];          // 64 weights packed
    const float4* wr = (const float4*)(Whh + (size_t)grow * 128 + half * 64);
#pragma unroll
    for (int q = 0; q < 16; q++) {
        float4 v = wr[q];
        w2[2*q]   = pk2(v.x, v.y);
        w2[2*q+1] = pk2(v.z, v.w);
    }

    unsigned bar      = smem_u32(&mbar_store);
    unsigned peer_bar = mapa_u32(bar, rank ^ 1);
    unsigned ga_u32   = smem_u32(&ga[0][0]);
    unsigned peer_ga  = mapa_u32(ga_u32 + (unsigned)grow * 4, rank ^ 1); // +p*2048 per step

    float c = 0.f;
    if (t < 128) { hs[t] = g_Hf[dir][b][t]; c = g_Cf[dir][b][t]; }
    if (t == 0) mbar_init(bar, 32);     // 16 local + 16 remote elected arrivals
    __syncthreads();
    cluster_sync_();                    // mbar + hs visible cluster-wide

    int stp = dir ? -1 : 1;
    int s   = dir ? (len - 1) : 0;
    const float* G = g_G2 + (size_t)base * 1024 + dir * 512 + grow;
    float xg = (half == 0) ? G[(size_t)s * 1024] : 0.f;
    bool isg = (rank == 1) && (row < 128);      // g-gate rows 256..383
    float* Orow = g_OUT2 + (size_t)base * 256 + dir * 128;

    for (int it = 0; it < len; it++) {
        int p = it & 1;
        float xgn = 0.f;
        if (half == 0 && it + 1 < len) xgn = G[(size_t)(s + stp) * 1024];

        unsigned long long A = pk2(xg, 0.f), B = pk2(0.f, 0.f);
        const ulonglong2* h2 = (const ulonglong2*)(hs + half * 64);
#pragma unroll
        for (int q = 0; q < 16; q++) {
            ulonglong2 hv = h2[q];
            A = ffma2(w2[2*q],   hv.x, A);
            B = ffma2(w2[2*q+1], hv.y, B);
        }
        float alo, ahi, blo, bhi;
        unpk2(A, alo, ahi); unpk2(B, blo, bhi);
        float part = (alo + blo) + (ahi + bhi);
        float tot  = part + __shfl_xor_sync(0xFFFFFFFFu, part, 1);
        if (half == 0) {
            float act = isg ? tanh_fast(tot) : sig_fast(tot);
            ga[p][grow] = act;
            st_shared_cluster_f32(peer_ga + (unsigned)p * 2048, act);
        }
        __syncwarp();
        if ((t & 31) == 0) {            // elected: lane0 arrives for its whole warp
            mbar_arrive_local(bar);
            mbar_arrive_remote(peer_bar);
        }
        if (t < 128) {
            mbar_wait_cluster(bar, (unsigned)p);
            float iv = ga[p][t], fv = ga[p][128 + t], gv = ga[p][256 + t], ov = ga[p][384 + t];
            c = fmaf(fv, c, iv * gv);
            float hn = ov * tanh_fast(c);
            hs[t] = hn;
            if (rank == 0) Orow[(size_t)s * 256 + t] = hn;
        }
        __syncthreads();
        s += stp;
        xg = xgn;
    }
    cluster_sync_();                    // lifetime: no early exit while peer sends
}

// ---------------- emission: warp per packed row ----------------
__global__ void k_emission(const float* __restrict__ Wlin, const float* __restrict__ blin)
{
    int total = g_segoff[256];
    int gw   = (blockIdx.x * blockDim.x + threadIdx.x) >> 5;
    int nw   = (gridDim.x * blockDim.x) >> 5;
    int lane = threadIdx.x & 31;
    int k = lane & 15, half = lane >> 4;
    const float4* wr = (const float4*)(Wlin + k * 256 + half * 128);
    float4 wreg[32];
#pragma unroll
    for (int q = 0; q < 32; q++) wreg[q] = wr[q];
    float bk = blin[k];
    for (int r = gw; r < total; r += nw) {
        const float4* xr = (const float4*)(g_OUT2 + (size_t)r * 256 + half * 128);
        float a = 0.f;
#pragma unroll
        for (int q = 0; q < 32; q++) {
            float4 x = xr[q], wv = wreg[q];
            a = fmaf(x.x, wv.x, a); a = fmaf(x.y, wv.y, a);
            a = fmaf(x.z, wv.z, a); a = fmaf(x.w, wv.w, a);
        }
        a += __shfl_xor_sync(0xFFFFFFFFu, a, 16);
        if (lane < 16) g_EM[(size_t)r * 16 + k] = a + bk;
    }
}

// ---------------- Viterbi: one block per batch, smem history ----------------
__global__ __launch_bounds__(32, 1) void k_viterbi(
    const float* __restrict__ startv, const float* __restrict__ trans,
    const float* __restrict__ endv, float* __restrict__ out)
{
    __shared__ unsigned char hist[(TTOT - 1) * 16];
    int b    = blockIdx.x;
    int lane = threadIdx.x;
    int j    = lane & 15;
    int base = g_segoff[b * 8];
    int L    = g_segoff[b * 8 + 8] - base;
    float trC[16];
#pragma unroll
    for (int i = 0; i < 16; i++) trC[i] = trans[i * 16 + j];
    const float* em = g_EM + (size_t)base * 16;

    float sc  = startv[j] + em[j];
    float emj = em[16 + j];
    for (int t = 1; t < L; t++) {
        float em_next = (t + 1 < L) ? em[(t + 1) * 16 + j] : 0.0f;
        float best = -3.4e38f; int bi = 0;
#pragma unroll
        for (int i = 0; i < 16; i++) {
            float v = (__shfl_sync(0xFFFFFFFFu, sc, i) + trC[i]) + emj;
            if (v > best) { best = v; bi = i; }
        }
        sc = best;
        if (lane < 16) hist[(t - 1) * 16 + j] = (unsigned char)bi;
        emj = em_next;
    }
    float fin = sc + endv[j];
    float bestv = -3.4e38f; int last = 0;
#pragma unroll
    for (int i = 0; i < 16; i++) {
        float v = __shfl_sync(0xFFFFFFFFu, fin, i);
        if (v > bestv) { bestv = v; last = i; }
    }
    __syncwarp();
    if (lane == 0) {
        out[32768 + b] = bestv;
        int cur = last;
        out[(TTOT - 1) * 32 + b] = (float)cur;
        for (int t = TTOT - 1; t >= L; t--) out[(t - 1) * 32 + b] = (float)cur;
        for (int t = L - 1; t >= 1; t--) {
            cur = hist[(t - 1) * 16 + cur];
            out[(t - 1) * 32 + b] = (float)cur;
        }
    }
}

// ---------------- launch ----------------
extern "C" void kernel_launch(void* const* d_in, const int* in_sizes, int n_in,
                              void* d_out, int out_size)
{
    const int*   texts   = (const int*)  d_in[0];
    const int*   lengths = (const int*)  d_in[1];
    const float* emb     = (const float*)d_in[2];
    const float* Wih_f   = (const float*)d_in[3];
    const float* Whh_f   = (const float*)d_in[4];
    const float* bih_f   = (const float*)d_in[5];
    const float* bhh_f   = (const float*)d_in[6];
    const float* Wih_b   = (const float*)d_in[7];
    const float* Whh_b   = (const float*)d_in[8];
    const float* bih_b   = (const float*)d_in[9];
    const float* bhh_b   = (const float*)d_in[10];
    const float* Wlin    = (const float*)d_in[11];
    const float* blin    = (const float*)d_in[12];
    const float* crf_s   = (const float*)d_in[13];
    const float* crf_t   = (const float*)d_in[14];
    const float* crf_e   = (const float*)d_in[15];
    float* out = (float*)d_out;

    cudaFuncSetAttribute(k_lstm1, cudaFuncAttributeMaxDynamicSharedMemorySize, SMEM_LSTM);
    cudaFuncSetAttribute(k_gemm3<1>, cudaFuncAttributeMaxDynamicSharedMemorySize, SMEM_G3);
    cudaFuncSetAttribute(k_gemm3<0>, cudaFuncAttributeMaxDynamicSharedMemorySize, SMEM_G3);

    float *pG1, *pP2, *pG2;
    cudaGetSymbolAddress((void**)&pG1, g_G1);
    cudaGetSymbolAddress((void**)&pP2, g_P2);
    cudaGetSymbolAddress((void**)&pG2, g_G2);

    k_prep<<<257, 256>>>(Wih_f, Wih_b, bih_f, bhh_f, bih_b, bhh_b, lengths);
    k_rowmap<<<256, 128>>>(texts, lengths);
    k_gemm3<1><<<dim3(256, 8), 256, SMEM_G3>>>(emb, pG1);
    k_lstm1<<<512, 512, SMEM_LSTM>>>(lengths, Whh_f, Whh_b);
    k_gemm3<0><<<dim3(256, 8), 256, SMEM_G3>>>(pP2, pG2);
    k_lstm2c<<<128, 512>>>(Whh_f, Whh_b);
    k_emission<<<148, 256>>>(Wlin, blin);
    k_viterbi<<<32, 32>>>(crf_s, crf_t, crf_e, out);
}

// round 14
// speedup vs baseline: 1.1651x; 1.0111x over previous
#include <cuda_runtime.h>
#include <cstdint>
#include <mma.h>
#include <math.h>
using namespace nvcuda;

#define BATCH 32
#define NSEGC 8
#define SLEN  128
#define TTOT  1024
#define KTAG  16
#define MROWS 32768

// ---------------- device scratch ----------------
__device__ float g_G1 [(size_t)MROWS * 1024];   // stage1 x-gates (packed rows)
__device__ float g_P2 [(size_t)MROWS * 256];    // packed lstm2 input (= packed stage1 out)
__device__ float g_G2 [(size_t)MROWS * 1024];   // stage2 x-gates (packed rows)
__device__ float g_OUT2[(size_t)MROWS * 256];   // stage2 outputs (packed)
__device__ float g_EM [(size_t)MROWS * KTAG];   // emissions (packed)
__device__ float g_Whi[1024 * 256];             // tf32-hi of [Wf;Wb]
__device__ float g_Wlo[1024 * 256];             // tf32-lo of [Wf;Wb]
__device__ float g_bias[1024];                  // bih+bhh, f then b
__device__ int   g_segoff[257];
__device__ int   g_order[256];                  // segments sorted by descending length
__device__ int   g_tokmap[MROWS];
__device__ float g_Hf[2][BATCH][128];
__device__ float g_Cf[2][BATCH][128];

// ---------------- helpers ----------------
__device__ __forceinline__ float f2tf(float x)
{
    float r;
    asm("cvt.rna.tf32.f32 %0, %1;" : "=f"(r) : "f"(x));
    return r;
}
__device__ __forceinline__ float sig_fast(float x)
{
    return __fdividef(1.0f, 1.0f + __expf(-x));
}
__device__ __forceinline__ float tanh_fast(float x)
{
    return 1.0f - 2.0f * __fdividef(1.0f, 1.0f + __expf(2.0f * x));
}
// packed fp32x2 FMA (Blackwell FFMA2; PTX-only form)
__device__ __forceinline__ unsigned long long ffma2(
    unsigned long long a, unsigned long long b, unsigned long long c)
{
    unsigned long long d;
    asm("fma.rn.f32x2 %0, %1, %2, %3;" : "=l"(d) : "l"(a), "l"(b), "l"(c));
    return d;
}
__device__ __forceinline__ unsigned long long pk2(float lo, float hi)
{
    unsigned long long r;
    asm("mov.b64 %0, {%1, %2};" : "=l"(r) : "f"(lo), "f"(hi));
    return r;
}
__device__ __forceinline__ void unpk2(unsigned long long v, float& lo, float& hi)
{
    asm("mov.b64 {%0, %1}, %2;" : "=f"(lo), "=f"(hi) : "l"(v));
}
__device__ __forceinline__ unsigned smem_u32(const void* p)
{
    return (unsigned)__cvta_generic_to_shared(p);
}
__device__ __forceinline__ unsigned mapa_u32(unsigned a, unsigned r)
{
    unsigned d;
    asm("mapa.shared::cluster.u32 %0, %1, %2;" : "=r"(d) : "r"(a), "r"(r));
    return d;
}
__device__ __forceinline__ void mbar_init(unsigned a, unsigned cnt)
{
    asm volatile("mbarrier.init.shared.b64 [%0], %1;" :: "r"(a), "r"(cnt) : "memory");
}
__device__ __forceinline__ void mbar_arrive_local(unsigned a)
{
    asm volatile("mbarrier.arrive.shared::cta.b64 _, [%0];" :: "r"(a) : "memory");
}
__device__ __forceinline__ void mbar_arrive_remote(unsigned a)
{
    asm volatile("mbarrier.arrive.release.cluster.shared::cluster.b64 _, [%0];"
                 :: "r"(a) : "memory");
}
__device__ __forceinline__ void mbar_wait_cluster(unsigned a, unsigned phase)
{
    asm volatile(
        "{\n\t"
        ".reg .pred P;\n\t"
        "WLOOP%=:\n\t"
        "mbarrier.try_wait.parity.acquire.cluster.shared::cta.b64 P, [%0], %1;\n\t"
        "@!P bra WLOOP%=;\n\t"
        "}"
        :: "r"(a), "r"(phase) : "memory");
}
__device__ __forceinline__ void st_shared_cluster_f32(unsigned a, float v)
{
    asm volatile("st.shared::cluster.f32 [%0], %1;" :: "r"(a), "f"(v) : "memory");
}
__device__ __forceinline__ void cluster_sync_()
{
    asm volatile("barrier.cluster.arrive.aligned;" ::: "memory");
    asm volatile("barrier.cluster.wait.aligned;" ::: "memory");
}

// ---------------- prep: offsets + length sort + weight preconversion ----------------
__global__ void k_prep(const float* __restrict__ Wf, const float* __restrict__ Wb,
                       const float* __restrict__ b1f, const float* __restrict__ b2f,
                       const float* __restrict__ b1b, const float* __restrict__ b2b,
                       const int* __restrict__ lengths)
{
    if (blockIdx.x == 256) {
        __shared__ int slen[256];
        int t = threadIdx.x;
        slen[t] = lengths[t];
        __syncthreads();
        if (t < 32) {
            int v[8], s = 0;
#pragma unroll
            for (int i = 0; i < 8; i++) { v[i] = slen[t * 8 + i]; s += v[i]; }
            int inc = s;
#pragma unroll
            for (int d = 1; d < 32; d <<= 1) {
                int o = __shfl_up_sync(0xFFFFFFFFu, inc, d);
                if (t >= d) inc += o;
            }
            int run = inc - s;
#pragma unroll
            for (int i = 0; i < 8; i++) { g_segoff[t * 8 + i] = run; run += v[i]; }
            if (t == 31) g_segoff[256] = run;
        }
        int li = slen[t];
        int rank = 0;
#pragma unroll 8
        for (int j = 0; j < 256; j++) {
            int lj = slen[j];
            rank += (lj > li) || (lj == li && j < t);
        }
        g_order[rank] = t;
        return;
    }
    int idx = blockIdx.x * 256 + threadIdx.x;
#pragma unroll
    for (int e = 0; e < 4; e++) {
        int i = idx * 4 + e;
        int n = i >> 8, k = i & 255;
        float v = (n < 512) ? Wf[n * 256 + k] : Wb[(n - 512) * 256 + k];
        float hi = f2tf(v);
        g_Whi[i] = hi;
        g_Wlo[i] = f2tf(v - hi);
    }
    if (idx < 1024) {
        g_bias[idx] = (idx < 512) ? (b1f[idx] + b2f[idx])
                                  : (b1b[idx - 512] + b2b[idx - 512]);
    }
}

__global__ void k_rowmap(const int* __restrict__ texts, const int* __restrict__ lengths)
{
    int bs = blockIdx.x;
    int len = lengths[bs];
    int off = g_segoff[bs];
    int s = threadIdx.x;
    if (s < len) g_tokmap[off + s] = texts[bs * 128 + s];
}

// ---------------- 3xTF32 tensor-core GEMM, preconverted weights ----------------
#define SMEM_G3 ((4 * 128 * 40 + 16 * 136) * 4)

template<int GATHER>
__global__ __launch_bounds__(256, 2) void k_gemm3(
    const float* __restrict__ A, float* __restrict__ C)
{
    int total = g_segoff[256];
    int bm = blockIdx.x * 128;
    if (bm >= total) return;
    int bn = blockIdx.y * 128;

    extern __shared__ float sm[];
    float* Ash = sm;                       // [128][40]
    float* Asl = sm + 128 * 40;
    float* Bsh = sm + 2 * 128 * 40;
    float* Bsl = sm + 3 * 128 * 40;
    float* bias_s = sm + 4 * 128 * 40;     // [16][136]

    int tid = threadIdx.x;
    for (int i = tid; i < 16 * 128; i += 256) {
        int r = i >> 7, c = i & 127;
        bias_s[r * 136 + c] = g_bias[bn + c];
    }

    int r0 = tid >> 3;
    int f4 = (tid & 7) * 4;
    const float* arow[4];
#pragma unroll
    for (int p = 0; p < 4; p++) {
        int pr = bm + r0 + 32 * p;
        if (GATHER) {
            int tok = (pr < total) ? g_tokmap[pr] : 0;
            arow[p] = A + (size_t)tok * 256;
        } else {
            arow[p] = A + (size_t)pr * 256;
        }
    }
    const float* whrow = g_Whi + (size_t)(bn + r0) * 256;
    const float* wlrow = g_Wlo + (size_t)(bn + r0) * 256;

    int wid = tid >> 5;
    int lm = (wid & 3) * 32;
    int ln = (wid >> 2) * 64;

    wmma::fragment<wmma::accumulator, 16, 16, 8, float> acc[2][4];
    __syncthreads();
#pragma unroll
    for (int mi = 0; mi < 2; mi++)
#pragma unroll
        for (int ni = 0; ni < 4; ni++)
            wmma::load_matrix_sync(acc[mi][ni], bias_s + ln + ni * 16, 136,
                                   wmma::mem_row_major);

    for (int k0 = 0; k0 < 256; k0 += 32) {
        float4 av[4], bh4[4], bl4[4];
#pragma unroll
        for (int p = 0; p < 4; p++) {
            av[p]  = *(const float4*)(arow[p] + k0 + f4);
            bh4[p] = *(const float4*)(whrow + (size_t)p * 32 * 256 + k0 + f4);
            bl4[p] = *(const float4*)(wlrow + (size_t)p * 32 * 256 + k0 + f4);
        }
        __syncthreads();
#pragma unroll
        for (int p = 0; p < 4; p++) {
            int row = (r0 + 32 * p) * 40 + f4;
            float h0 = f2tf(av[p].x), h1 = f2tf(av[p].y),
                  h2 = f2tf(av[p].z), h3 = f2tf(av[p].w);
            *(float4*)&Ash[row] = make_float4(h0, h1, h2, h3);
            *(float4*)&Asl[row] = make_float4(f2tf(av[p].x - h0), f2tf(av[p].y - h1),
                                              f2tf(av[p].z - h2), f2tf(av[p].w - h3));
            *(float4*)&Bsh[row] = bh4[p];
            *(float4*)&Bsl[row] = bl4[p];
        }
        __syncthreads();
#pragma unroll
        for (int ks = 0; ks < 4; ks++) {
            wmma::fragment<wmma::matrix_a, 16, 16, 8, wmma::precision::tf32,
                           wmma::row_major> ah[2], al[2];
#pragma unroll
            for (int mi = 0; mi < 2; mi++) {
                wmma::load_matrix_sync(ah[mi], Ash + (lm + mi * 16) * 40 + ks * 8, 40);
                wmma::load_matrix_sync(al[mi], Asl + (lm + mi * 16) * 40 + ks * 8, 40);
            }
#pragma unroll
            for (int ni = 0; ni < 4; ni++) {
                wmma::fragment<wmma::matrix_b, 16, 16, 8, wmma::precision::tf32,
                               wmma::col_major> bh, bl;
                wmma::load_matrix_sync(bh, Bsh + (ln + ni * 16) * 40 + ks * 8, 40);
                wmma::load_matrix_sync(bl, Bsl + (ln + ni * 16) * 40 + ks * 8, 40);
#pragma unroll
                for (int mi = 0; mi < 2; mi++) {
                    wmma::mma_sync(acc[mi][ni], ah[mi], bl, acc[mi][ni]);
                    wmma::mma_sync(acc[mi][ni], al[mi], bh, acc[mi][ni]);
                    wmma::mma_sync(acc[mi][ni], ah[mi], bh, acc[mi][ni]);
                }
            }
        }
    }
#pragma unroll
    for (int mi = 0; mi < 2; mi++)
#pragma unroll
        for (int ni = 0; ni < 4; ni++)
            wmma::store_matrix_sync(
                C + (size_t)(bm + lm + mi * 16) * 1024 + bn + ln + ni * 16,
                acc[mi][ni], 1024, wmma::mem_row_major);
}

// ---------------- LSTM1 recurrent core (FFMA2 + depth-4 xg prefetch) --------------
#define SMEM_LSTM ((512 * 68 + 128 + 512) * 4)

__device__ __forceinline__ void lstm_run(
    const float* __restrict__ Whh, const float* __restrict__ Gbase,
    float* __restrict__ Obase, int len, int dir, int t,
    float* ws, float* hs, float* ga,
    float h_init, float c_init, int write_final, int b)
{
    const float* wr = Whh + t * 128;
    unsigned long long w2[32];             // first 64 weights, packed pairs
#pragma unroll
    for (int q = 0; q < 16; q++) {
        float4 v = *(const float4*)(wr + q * 4);
        w2[2*q]   = pk2(v.x, v.y);
        w2[2*q+1] = pk2(v.z, v.w);
    }
    float* wsr = ws + t * 68;              // last 64 weights in smem (16B aligned)
#pragma unroll
    for (int q = 0; q < 16; q++)
        *(float4*)(wsr + 4 * q) = *(const float4*)(wr + 64 + 4 * q);

    float c = c_init;
    if (t < 128) hs[t] = h_init;
    __syncthreads();

    int s    = dir ? (len - 1) : 0;
    int step = dir ? -1 : 1;
    bool isg = ((t >> 7) == 2);
    // depth-4 register prefetch pipeline for the streaming xg loads
    float xp0, xp1, xp2, xp3;
    xp0 = Gbase[(size_t)s * 1024];
    xp1 = (1 < len) ? Gbase[(size_t)(s + step) * 1024] : 0.f;
    xp2 = (2 < len) ? Gbase[(size_t)(s + 2 * step) * 1024] : 0.f;
    xp3 = (3 < len) ? Gbase[(size_t)(s + 3 * step) * 1024] : 0.f;

    for (int it = 0; it < len; it++) {
        float xg = xp0;
        xp0 = xp1; xp1 = xp2; xp2 = xp3;
        xp3 = (it + 4 < len) ? Gbase[(size_t)(s + 4 * step) * 1024] : 0.f;

        unsigned long long A = pk2(xg, 0.f), B = pk2(0.f, 0.f);
        const ulonglong2* h2 = (const ulonglong2*)hs;        // 128 floats = 32 u64
#pragma unroll
        for (int q = 0; q < 16; q++) {
            ulonglong2 hv = h2[q];
            A = ffma2(w2[2*q],   hv.x, A);
            B = ffma2(w2[2*q+1], hv.y, B);
        }
        const ulonglong2* w2s = (const ulonglong2*)wsr;
#pragma unroll
        for (int q = 0; q < 16; q++) {
            ulonglong2 wv = w2s[q];
            ulonglong2 hv = h2[16 + q];
            A = ffma2(wv.x, hv.x, A);
            B = ffma2(wv.y, hv.y, B);
        }
        float alo, ahi, blo, bhi;
        unpk2(A, alo, ahi); unpk2(B, blo, bhi);
        float acc = (alo + blo) + (ahi + bhi);
        ga[t] = isg ? tanh_fast(acc) : sig_fast(acc);
        __syncthreads();
        if (t < 128) {
            float iv = ga[t], fv = ga[128 + t], gv = ga[256 + t], ov = ga[384 + t];
            c = fmaf(fv, c, iv * gv);
            float hn = ov * tanh_fast(c);
            hs[t] = hn;
            Obase[(size_t)s * 256 + t] = hn;
        }
        __syncthreads();
        s += step;
    }
    if (write_final && t < 128) {
        g_Hf[dir][b][t] = hs[t];
        g_Cf[dir][b][t] = c;
    }
}

__global__ __launch_bounds__(512, 1) void k_lstm1(
    const int* __restrict__ lengths,
    const float* __restrict__ Whh_f, const float* __restrict__ Whh_b)
{
    extern __shared__ float sm[];
    float* ws = sm;
    float* hs = sm + 512 * 68;
    float* ga = hs + 128;
    int t   = threadIdx.x;
    int blk = blockIdx.x;
    int dir = blk >> 8;
    int bs  = g_order[blk & 255];          // LPT: longest segments first
    int len = lengths[bs];
    int off = g_segoff[bs];
    const float* Gbase = g_G1 + (size_t)off * 1024 + dir * 512 + t;
    float* Obase = g_P2 + (size_t)off * 256 + dir * 128;
    lstm_run(dir ? Whh_b : Whh_f, Gbase, Obase, len, dir, t, ws, hs, ga,
             0.0f, 0.0f, (bs & 7) == 7, bs >> 3);
}

// ---------------- LSTM2: 2-CTA cluster, reg weights + FFMA2 + xg prefetch ----------
__global__ __launch_bounds__(512, 1) __cluster_dims__(2, 1, 1)
void k_lstm2c(const float* __restrict__ Whh_f, const float* __restrict__ Whh_b)
{
    __shared__ float ga[2][512];
    __shared__ float hs[128];
    __shared__ __align__(8) unsigned long long mbar_store;

    unsigned rank;
    asm("mov.u32 %0, %%cluster_ctarank;" : "=r"(rank));
    int t   = threadIdx.x;
    int cid = blockIdx.x >> 1;          // cluster index: dir*32 + b
    int dir = cid >> 5;
    int b   = cid & 31;

    int base = g_segoff[b * 8];
    int len  = g_segoff[b * 8 + 8] - base;

    int row  = t >> 1, half = t & 1;
    int grow = (int)rank * 256 + row;   // global gate row 0..511

    const float* Whh = dir ? Whh_b : Whh_f;
    unsigned long long w2[32];          // 64 weights packed
    const float4* wr = (const float4*)(Whh + (size_t)grow * 128 + half * 64);
#pragma unroll
    for (int q = 0; q < 16; q++) {
        float4 v = wr[q];
        w2[2*q]   = pk2(v.x, v.y);
        w2[2*q+1] = pk2(v.z, v.w);
    }

    unsigned bar      = smem_u32(&mbar_store);
    unsigned peer_bar = mapa_u32(bar, rank ^ 1);
    unsigned ga_u32   = smem_u32(&ga[0][0]);
    unsigned peer_ga  = mapa_u32(ga_u32 + (unsigned)grow * 4, rank ^ 1); // +p*2048 per step

    float c = 0.f;
    if (t < 128) { hs[t] = g_Hf[dir][b][t]; c = g_Cf[dir][b][t]; }
    if (t == 0) mbar_init(bar, 32);     // 16 local + 16 remote elected arrivals
    __syncthreads();
    cluster_sync_();                    // mbar + hs visible cluster-wide

    int stp = dir ? -1 : 1;
    int s   = dir ? (len - 1) : 0;
    const float* G = g_G2 + (size_t)base * 1024 + dir * 512 + grow;
    bool isg = (rank == 1) && (row < 128);      // g-gate rows 256..383
    float* Orow = g_OUT2 + (size_t)base * 256 + dir * 128;

    // depth-4 register prefetch (half==0 threads only carry real values)
    float xp0 = 0.f, xp1 = 0.f, xp2 = 0.f, xp3 = 0.f;
    if (half == 0) {
        xp0 = G[(size_t)s * 1024];
        xp1 = (1 < len) ? G[(size_t)(s + stp) * 1024] : 0.f;
        xp2 = (2 < len) ? G[(size_t)(s + 2 * stp) * 1024] : 0.f;
        xp3 = (3 < len) ? G[(size_t)(s + 3 * stp) * 1024] : 0.f;
    }

    for (int it = 0; it < len; it++) {
        int p = it & 1;
        float xg = xp0;
        xp0 = xp1; xp1 = xp2; xp2 = xp3;
        xp3 = (half == 0 && it + 4 < len) ? G[(size_t)(s + 4 * stp) * 1024] : 0.f;

        unsigned long long A = pk2(xg, 0.f), B = pk2(0.f, 0.f);
        const ulonglong2* h2 = (const ulonglong2*)(hs + half * 64);
#pragma unroll
        for (int q = 0; q < 16; q++) {
            ulonglong2 hv = h2[q];
            A = ffma2(w2[2*q],   hv.x, A);
            B = ffma2(w2[2*q+1], hv.y, B);
        }
        float alo, ahi, blo, bhi;
        unpk2(A, alo, ahi); unpk2(B, blo, bhi);
        float part = (alo + blo) + (ahi + bhi);
        float tot  = part + __shfl_xor_sync(0xFFFFFFFFu, part, 1);
        if (half == 0) {
            float act = isg ? tanh_fast(tot) : sig_fast(tot);
            ga[p][grow] = act;
            st_shared_cluster_f32(peer_ga + (unsigned)p * 2048, act);
        }
        __syncwarp();
        if ((t & 31) == 0) {            // elected: lane0 arrives for its whole warp
            mbar_arrive_local(bar);
            mbar_arrive_remote(peer_bar);
        }
        if (t < 128) {
            mbar_wait_cluster(bar, (unsigned)p);
            float iv = ga[p][t], fv = ga[p][128 + t], gv = ga[p][256 + t], ov = ga[p][384 + t];
            c = fmaf(fv, c, iv * gv);
            float hn = ov * tanh_fast(c);
            hs[t] = hn;
            if (rank == 0) Orow[(size_t)s * 256 + t] = hn;
        }
        __syncthreads();
        s += stp;
    }
    cluster_sync_();                    // lifetime: no early exit while peer sends
}

// ---------------- emission: warp per packed row ----------------
__global__ void k_emission(const float* __restrict__ Wlin, const float* __restrict__ blin)
{
    int total = g_segoff[256];
    int gw   = (blockIdx.x * blockDim.x + threadIdx.x) >> 5;
    int nw   = (gridDim.x * blockDim.x) >> 5;
    int lane = threadIdx.x & 31;
    int k = lane & 15, half = lane >> 4;
    const float4* wr = (const float4*)(Wlin + k * 256 + half * 128);
    float4 wreg[32];
#pragma unroll
    for (int q = 0; q < 32; q++) wreg[q] = wr[q];
    float bk = blin[k];
    for (int r = gw; r < total; r += nw) {
        const float4* xr = (const float4*)(g_OUT2 + (size_t)r * 256 + half * 128);
        float a = 0.f;
#pragma unroll
        for (int q = 0; q < 32; q++) {
            float4 x = xr[q], wv = wreg[q];
            a = fmaf(x.x, wv.x, a); a = fmaf(x.y, wv.y, a);
            a = fmaf(x.z, wv.z, a); a = fmaf(x.w, wv.w, a);
        }
        a += __shfl_xor_sync(0xFFFFFFFFu, a, 16);
        if (lane < 16) g_EM[(size_t)r * 16 + k] = a + bk;
    }
}

// ---------------- Viterbi: one block per batch, smem history ----------------
__global__ __launch_bounds__(32, 1) void k_viterbi(
    const float* __restrict__ startv, const float* __restrict__ trans,
    const float* __restrict__ endv, float* __restrict__ out)
{
    __shared__ unsigned char hist[(TTOT - 1) * 16];
    int b    = blockIdx.x;
    int lane = threadIdx.x;
    int j    = lane & 15;
    int base = g_segoff[b * 8];
    int L    = g_segoff[b * 8 + 8] - base;
    float trC[16];
#pragma unroll
    for (int i = 0; i < 16; i++) trC[i] = trans[i * 16 + j];
    const float* em = g_EM + (size_t)base * 16;

    float sc  = startv[j] + em[j];
    float emj = em[16 + j];
    for (int t = 1; t < L; t++) {
        float em_next = (t + 1 < L) ? em[(t + 1) * 16 + j] : 0.0f;
        float best = -3.4e38f; int bi = 0;
#pragma unroll
        for (int i = 0; i < 16; i++) {
            float v = (__shfl_sync(0xFFFFFFFFu, sc, i) + trC[i]) + emj;
            if (v > best) { best = v; bi = i; }
        }
        sc = best;
        if (lane < 16) hist[(t - 1) * 16 + j] = (unsigned char)bi;
        emj = em_next;
    }
    float fin = sc + endv[j];
    float bestv = -3.4e38f; int last = 0;
#pragma unroll
    for (int i = 0; i < 16; i++) {
        float v = __shfl_sync(0xFFFFFFFFu, fin, i);
        if (v > bestv) { bestv = v; last = i; }
    }
    __syncwarp();
    if (lane == 0) {
        out[32768 + b] = bestv;
        int cur = last;
        out[(TTOT - 1) * 32 + b] = (float)cur;
        for (int t = TTOT - 1; t >= L; t--) out[(t - 1) * 32 + b] = (float)cur;
        for (int t = L - 1; t >= 1; t--) {
            cur = hist[(t - 1) * 16 + cur];
            out[(t - 1) * 32 + b] = (float)cur;
        }
    }
}

// ---------------- launch ----------------
extern "C" void kernel_launch(void* const* d_in, const int* in_sizes, int n_in,
                              void* d_out, int out_size)
{
    const int*   texts   = (const int*)  d_in[0];
    const int*   lengths = (const int*)  d_in[1];
    const float* emb     = (const float*)d_in[2];
    const float* Wih_f   = (const float*)d_in[3];
    const float* Whh_f   = (const float*)d_in[4];
    const float* bih_f   = (const float*)d_in[5];
    const float* bhh_f   = (const float*)d_in[6];
    const float* Wih_b   = (const float*)d_in[7];
    const float* Whh_b   = (const float*)d_in[8];
    const float* bih_b   = (const float*)d_in[9];
    const float* bhh_b   = (const float*)d_in[10];
    const float* Wlin    = (const float*)d_in[11];
    const float* blin    = (const float*)d_in[12];
    const float* crf_s   = (const float*)d_in[13];
    const float* crf_t   = (const float*)d_in[14];
    const float* crf_e   = (const float*)d_in[15];
    float* out = (float*)d_out;

    cudaFuncSetAttribute(k_lstm1, cudaFuncAttributeMaxDynamicSharedMemorySize, SMEM_LSTM);
    cudaFuncSetAttribute(k_gemm3<1>, cudaFuncAttributeMaxDynamicSharedMemorySize, SMEM_G3);
    cudaFuncSetAttribute(k_gemm3<0>, cudaFuncAttributeMaxDynamicSharedMemorySize, SMEM_G3);

    float *pG1, *pP2, *pG2;
    cudaGetSymbolAddress((void**)&pG1, g_G1);
    cudaGetSymbolAddress((void**)&pP2, g_P2);
    cudaGetSymbolAddress((void**)&pG2, g_G2);

    k_prep<<<257, 256>>>(Wih_f, Wih_b, bih_f, bhh_f, bih_b, bhh_b, lengths);
    k_rowmap<<<256, 128>>>(texts, lengths);
    k_gemm3<1><<<dim3(256, 8), 256, SMEM_G3>>>(emb, pG1);
    k_lstm1<<<512, 512, SMEM_LSTM>>>(lengths, Whh_f, Whh_b);
    k_gemm3<0><<<dim3(256, 8), 256, SMEM_G3>>>(pP2, pG2);
    k_lstm2c<<<128, 512>>>(Whh_f, Whh_b);
    k_emission<<<148, 256>>>(Wlin, blin);
    k_viterbi<<<32, 32>>>(crf_s, crf_t, crf_e, out);
}